// round 1
// baseline (speedup 1.0000x reference)
#include <cuda_runtime.h>
#include <math.h>

// Problem constants (must match reference)
#define BB 16
#define HH 120
#define WW 160
#define DD 401          // int(8000/20)+1
#define DEPTH_MAX 8000.0f
#define INV_BIN   (1.0f / 20.0f)
#define BIN_SIZE  20.0f
#define ZERO_EPS  1e-06f
#define SIG_EPS   (0.5f + 1e-08f)

// z = (bin - d)/SIG_EPS ; g = exp(-0.5 z^2) / (SIG_EPS * sqrt(2pi))
// Only the two flanking bins of d can be nonzero in fp32:
// any other bin has |bin - d| >= 10 -> |z| >= 20 -> exp(-200) == 0.0f exactly.

__global__ void __launch_bounds__(128)
dim_hist_kernel(const float* __restrict__ depth, float* __restrict__ out)
{
    const int bw = blockIdx.x;          // 0 .. B*W-1
    const int b  = bw / WW;
    const int w  = bw - b * WW;
    const int tid = threadIdx.x;

    __shared__ float acc[DD];
    __shared__ float sdep[HH];

    // zero accumulator
    #pragma unroll
    for (int i = tid; i < DD; i += 128) acc[i] = 0.0f;

    // gather this (b, :, w) column of depth (stride-W loads; tiny input, L2-friendly)
    for (int h = tid; h < HH; h += 128)
        sdep[h] = depth[(b * HH + h) * WW + w];

    __syncthreads();

    const float inv_sig = 1.0f / SIG_EPS;                 // 1/(sigma+eps)
    const float norm    = 0.3989422804014327f * inv_sig;  // 1/((sigma+eps)*sqrt(2pi))

    for (int h = tid; h < HH; h += 128) {
        float d = sdep[h];
        // valid: finite, d <= DEPTH_MAX, d > ZERO_EPS
        if (!(isfinite(d) && d <= DEPTH_MAX && d > ZERO_EPS)) continue;

        int k0 = (int)floorf(d * INV_BIN);   // flanking bins k0, k0+1
        #pragma unroll
        for (int j = 0; j < 2; ++j) {
            int k = k0 + j;
            if (k < 0 || k >= DD) continue;
            float z = ((float)k * BIN_SIZE - d) * inv_sig;
            float g = expf(-0.5f * z * z) * norm;   // underflows to 0 beyond ~6.6 units
            if (g != 0.0f) atomicAdd(&acc[k], g);
        }
    }

    __syncthreads();

    // coalesced row write: out[b, w, :]
    float* o = out + ((size_t)b * WW + w) * DD;
    #pragma unroll
    for (int i = tid; i < DD; i += 128) o[i] = acc[i];
}

extern "C" void kernel_launch(void* const* d_in, const int* in_sizes, int n_in,
                              void* d_out, int out_size)
{
    const float* depth = (const float*)d_in[0];
    float* out = (float*)d_out;
    dim_hist_kernel<<<BB * WW, 128>>>(depth, out);
}

// round 2
// speedup vs baseline: 1.3350x; 1.3350x over previous
#include <cuda_runtime.h>
#include <math.h>

// Problem constants (must match reference)
#define BB 16
#define HH 120
#define WW 160
#define DD 401          // int(8000/20)+1
#define WT 4            // w-tile per block -> contiguous, 16B-aligned output span
#define DEPTH_MAX 8000.0f
#define INV_BIN   (1.0f / 20.0f)
#define BIN_SIZE  20.0f
#define ZERO_EPS  1e-06f
#define SIG_EPS   (0.5f + 1e-08f)

// Sparsity facts (fp32):
//  - only the two bins flanking d can be nonzero: any other bin has |z| >= 40 -> exp == 0
//  - of the two flanks, at most one is ever nonzero (needs distance < 6.6; flanks are 20 apart),
//    so the g != 0 guard skips ~all second atomics and ~34% of first ones.

__global__ void __launch_bounds__(128)
dim_hist_kernel(const float* __restrict__ depth, float* __restrict__ out)
{
    const int blk = blockIdx.x;              // 0 .. BB*WW/WT - 1  (640)
    const int b   = blk / (WW / WT);
    const int w0  = (blk - b * (WW / WT)) * WT;
    const int tid = threadIdx.x;

    __shared__ __align__(16) float acc[WT][DD];   // 6416 B

    // zero accumulator (flat, vector-friendly)
    float* af = &acc[0][0];
    #pragma unroll
    for (int i = tid; i < WT * DD; i += 128) af[i] = 0.0f;
    __syncthreads();

    const float inv_sig = 1.0f / SIG_EPS;                 // 1/(sigma+eps)
    const float norm    = 0.3989422804014327f * inv_sig;  // 1/((sigma+eps)*sqrt(2pi))

    if (tid < HH) {
        // aligned 16B load: depth[b, h=tid, w0..w0+3]
        const float4 d4 = *(const float4*)(depth + ((size_t)b * HH + tid) * WW + w0);
        const float dv[WT] = {d4.x, d4.y, d4.z, d4.w};

        #pragma unroll
        for (int wi = 0; wi < WT; ++wi) {
            float d = dv[wi];
            if (!(isfinite(d) && d <= DEPTH_MAX && d > ZERO_EPS)) continue;

            int k0 = (int)floorf(d * INV_BIN);   // flanking bins k0, k0+1
            #pragma unroll
            for (int j = 0; j < 2; ++j) {
                int k = k0 + j;
                if (k < 0 || k >= DD) continue;
                float z = ((float)k * BIN_SIZE - d) * inv_sig;
                float g = __expf(-0.5f * z * z) * norm;   // MUFU.EX2 path
                if (g != 0.0f) atomicAdd(&acc[wi][k], g);
            }
        }
    }
    __syncthreads();

    // contiguous output span: out[b, w0..w0+3, :] = WT*DD = 1604 floats = 401 float4s,
    // 16B-aligned because (b*WW + w0) % 4 == 0 and 4*1604 % 16 == 0.
    float4* o = (float4*)(out + ((size_t)b * WW + w0) * DD);
    const float4* a4 = (const float4*)af;
    #pragma unroll
    for (int i = tid; i < (WT * DD) / 4; i += 128) o[i] = a4[i];
}

extern "C" void kernel_launch(void* const* d_in, const int* in_sizes, int n_in,
                              void* d_out, int out_size)
{
    const float* depth = (const float*)d_in[0];
    float* out = (float*)d_out;
    dim_hist_kernel<<<(BB * WW) / WT, 128>>>(depth, out);
}